// round 15
// baseline (speedup 1.0000x reference)
#include <cuda_runtime.h>
#include <cuda_bf16.h>
#include <math.h>
#include <stdint.h>

// ---------------- problem constants ----------------
#define BB     8
#define NTOK   1024
#define DD     256
#define LL     4
#define MFF    1024
#define HH     8
#define DHEAD  32
#define NT     (BB*NTOK)      // 8192 tokens
#define KC     64             // clusters
#define KM_IT  10
#define SB     64             // segsum point-blocks (128 points each)
#define QKVS   768            // combined qkv row stride
#define NSPLIT 4              // split-K factor for ffn-down

// weight-transpose scratch offsets (elements, per layer base = l*786432)
#define WT_LAYER 786432
#define WQKV_OFF 0
#define WO_OFF   196608
#define W1_OFF   262144
#define W2_OFF   524288

// ---------------- scratch (static device globals; no allocation allowed) ----
__device__ float g_x   [NT*DD];          // running residual stream (fp32)
__device__ __nv_bfloat16 g_qkvh[NT*QKVS];
__device__ __nv_bfloat16 g_qkvl[NT*QKVS];
__device__ __nv_bfloat16 g_xnh[NT*DD];
__device__ __nv_bfloat16 g_xnl[NT*DD];
__device__ __nv_bfloat16 g_aoh[NT*DD];
__device__ __nv_bfloat16 g_aol[NT*DD];
__device__ __nv_bfloat16 g_hh [NT*MFF];
__device__ __nv_bfloat16 g_hl [NT*MFF];
__device__ __nv_bfloat16 g_wth[LL*WT_LAYER];
__device__ __nv_bfloat16 g_wtl[LL*WT_LAYER];
__device__ float g_psum[NSPLIT*NT*DD];   // split-K partials (32 MB)
__device__ float g_xsq [NT];
__device__ float g_cent[KC*DD];
__device__ float g_csq [KC];
__device__ int   g_lab [NT];
__device__ float g_cpro[KC*DD];
__device__ float g_part[SB*KC*DD];
__device__ float g_pcnt[SB*KC];

// ---------------- small helpers ----------------
__device__ __forceinline__ float gelu_f(float x) {
    return 0.5f * x * (1.0f + erff(x * 0.7071067811865476f));
}
__device__ __forceinline__ float warpSum(float v) {
    #pragma unroll
    for (int o = 16; o > 0; o >>= 1) v += __shfl_xor_sync(0xffffffffu, v, o);
    return v;
}
__device__ __forceinline__ float blockSum256(float v) {
    __shared__ float red[8];
    int t = threadIdx.x;
    v = warpSum(v);
    if ((t & 31) == 0) red[t >> 5] = v;
    __syncthreads();
    float s = 0.f;
    if (t == 0) {
        #pragma unroll
        for (int i = 0; i < 8; i++) s += red[i];
        red[0] = s;
    }
    __syncthreads();
    s = red[0];
    __syncthreads();
    return s;
}
__device__ __forceinline__ void splitf(float v, __nv_bfloat16& h, __nv_bfloat16& l) {
    h = __float2bfloat16(v);
    l = __float2bfloat16(v - __bfloat162float(h));
}
__device__ __forceinline__ void pack_split(float a, float b, uint32_t& hi, uint32_t& lo) {
    __nv_bfloat16 ah, al, bh, bl;
    splitf(a, ah, al); splitf(b, bh, bl);
    __nv_bfloat162 h2 = __halves2bfloat162(ah, bh);
    __nv_bfloat162 l2 = __halves2bfloat162(al, bl);
    hi = *(uint32_t*)&h2; lo = *(uint32_t*)&l2;
}
__device__ __forceinline__ uint32_t smem_u32(const void* p) {
    uint32_t a;
    asm("{ .reg .u64 t; cvta.to.shared.u64 t, %1; cvt.u32.u64 %0, t; }" : "=r"(a) : "l"(p));
    return a;
}

// ---------------- mma.sync helpers ----------------
__device__ __forceinline__ void ldm_x4(uint32_t* r, uint32_t addr) {
    asm volatile("ldmatrix.sync.aligned.m8n8.x4.shared.b16 {%0,%1,%2,%3}, [%4];"
                 : "=r"(r[0]), "=r"(r[1]), "=r"(r[2]), "=r"(r[3]) : "r"(addr));
}
__device__ __forceinline__ void mma_bf16(float* c, const uint32_t* a, const uint32_t* b) {
    asm volatile(
        "mma.sync.aligned.m16n8k16.row.col.f32.bf16.bf16.f32 "
        "{%0,%1,%2,%3}, {%4,%5,%6,%7}, {%8,%9}, {%0,%1,%2,%3};"
        : "+f"(c[0]), "+f"(c[1]), "+f"(c[2]), "+f"(c[3])
        : "r"(a[0]), "r"(a[1]), "r"(a[2]), "r"(a[3]), "r"(b[0]), "r"(b[1]));
}
__device__ __forceinline__ void cp16(uint32_t dst, const void* src) {
    asm volatile("cp.async.cg.shared.global [%0], [%1], 16;"
                 :: "r"(dst), "l"(src) : "memory");
}

// ---------------- layernorm: one WARP per row; emits split-bf16 --------------
__global__ void ln_kernel(const float* __restrict__ x, const float* __restrict__ g,
                          const float* __restrict__ b,
                          __nv_bfloat16* __restrict__ oh, __nv_bfloat16* __restrict__ ol) {
    int row  = (blockIdx.x * blockDim.x + threadIdx.x) >> 5;
    int lane = threadIdx.x & 31;
    const float* xp = x + (size_t)row * DD;
    float4 a = *(const float4*)&xp[lane * 4];
    float4 c = *(const float4*)&xp[128 + lane * 4];
    float s = a.x + a.y + a.z + a.w + c.x + c.y + c.z + c.w;
    float mean = warpSum(s) * (1.0f / DD);
    float4 da = make_float4(a.x - mean, a.y - mean, a.z - mean, a.w - mean);
    float4 dc = make_float4(c.x - mean, c.y - mean, c.z - mean, c.w - mean);
    float v = da.x*da.x + da.y*da.y + da.z*da.z + da.w*da.w
            + dc.x*dc.x + dc.y*dc.y + dc.z*dc.z + dc.w*dc.w;
    float rs = rsqrtf(warpSum(v) * (1.0f / DD) + 1e-5f);
    float4 g0 = *(const float4*)&g[lane * 4];
    float4 g1 = *(const float4*)&g[128 + lane * 4];
    float4 b0 = *(const float4*)&b[lane * 4];
    float4 b1 = *(const float4*)&b[128 + lane * 4];
    float o0[4] = { da.x*rs*g0.x + b0.x, da.y*rs*g0.y + b0.y,
                    da.z*rs*g0.z + b0.z, da.w*rs*g0.w + b0.w };
    float o1[4] = { dc.x*rs*g1.x + b1.x, dc.y*rs*g1.y + b1.y,
                    dc.z*rs*g1.z + b1.z, dc.w*rs*g1.w + b1.w };
    size_t base = (size_t)row * DD;
    #pragma unroll
    for (int j = 0; j < 2; j++) {
        uint32_t uh, ul;
        pack_split(o0[j*2+0], o0[j*2+1], uh, ul);
        *(uint32_t*)&oh[base + lane*4 + j*2] = uh;
        *(uint32_t*)&ol[base + lane*4 + j*2] = ul;
        pack_split(o1[j*2+0], o1[j*2+1], uh, ul);
        *(uint32_t*)&oh[base + 128 + lane*4 + j*2] = uh;
        *(uint32_t*)&ol[base + 128 + lane*4 + j*2] = ul;
    }
}

// ---------------- row sum-of-squares ----------------
__global__ void rowsumsq_kernel(const float* __restrict__ x, float* __restrict__ out) {
    int row  = (blockIdx.x * blockDim.x + threadIdx.x) >> 5;
    int lane = threadIdx.x & 31;
    const float* xp = x + (size_t)row * DD;
    float4 a = *(const float4*)&xp[lane * 4];
    float4 c = *(const float4*)&xp[128 + lane * 4];
    float s = a.x*a.x + a.y*a.y + a.z*a.z + a.w*a.w
            + c.x*c.x + c.y*c.y + c.z*c.z + c.w*c.w;
    s = warpSum(s);
    if (lane == 0) out[row] = s;
}

// -------- weight transpose + bf16 split (batched over layers) ----------------
__global__ void wsplit_kernel(const float* __restrict__ W,
                              __nv_bfloat16* __restrict__ oh, __nv_bfloat16* __restrict__ ol,
                              int K, int N, int strideW, int strideO) {
    __shared__ float tile[32][33];
    const int l = blockIdx.z;
    const float* Wl = W + (size_t)l * strideW;
    __nv_bfloat16* ohl = oh + (size_t)l * strideO;
    __nv_bfloat16* oll = ol + (size_t)l * strideO;
    int k0 = blockIdx.y * 32, n0 = blockIdx.x * 32;
    int tx = threadIdx.x, ty = threadIdx.y;   // 32 x 8
    #pragma unroll
    for (int j = 0; j < 4; j++)
        tile[ty + j*8][tx] = Wl[(size_t)(k0 + ty + j*8) * N + n0 + tx];
    __syncthreads();
    #pragma unroll
    for (int j = 0; j < 4; j++) {
        int n = ty + j*8;
        float v = tile[tx][n];
        size_t idx = (size_t)(n0 + n) * K + k0 + tx;
        __nv_bfloat16 h, l2; splitf(v, h, l2);
        ohl[idx] = h; oll[idx] = l2;
    }
}

// ---------------- split-bf16 GEMM on HMMA (128x128) --------------------------
// Optional split-K: blockIdx.z = K-slice; K = slice length, Kstride = full row
// stride. Slices write fp32 partials to C + z*M*N (bias/res/act must be null).
#define PADK   40
#define ARR_B  (128*PADK*2)
#define OFF_AH 0
#define OFF_AL (1*ARR_B)
#define OFF_BH (2*ARR_B)
#define OFF_BL (3*ARR_B)
#define BUF_B  (4*ARR_B)
#define GM_SMEM (2*BUF_B)               // 81920

__global__ __launch_bounds__(256, 2)
void gemm_mma(const __nv_bfloat16* __restrict__ Ahi, const __nv_bfloat16* __restrict__ Alo,
              const __nv_bfloat16* __restrict__ Bhi, const __nv_bfloat16* __restrict__ Blo,
              const float* __restrict__ bias, const float* __restrict__ res,
              float* __restrict__ C,
              __nv_bfloat16* __restrict__ Chi, __nv_bfloat16* __restrict__ Clo,
              int M, int N, int K, int Kstride, int act) {
    extern __shared__ char smem[];
    const uint32_t sm = smem_u32(smem);
    const int m0 = blockIdx.y * 128;
    const int n0 = blockIdx.x * 128;
    const int koff = blockIdx.z * K;
    const int t = threadIdx.x;
    const int wid = t >> 5, lid = t & 31;
    const int wm = wid & 3;
    const int wn = wid >> 2;
    const int NC = K >> 5;
    if (C) C += (size_t)blockIdx.z * ((size_t)M * N);

    float acc[2][8][4];
    #pragma unroll
    for (int i = 0; i < 2; i++)
        #pragma unroll
        for (int j = 0; j < 8; j++)
            #pragma unroll
            for (int q = 0; q < 4; q++) acc[i][j][q] = 0.f;

    auto issueChunk = [&](int c, int buf) {
        const int kb = koff + c * 32;
        const uint32_t base = sm + buf * BUF_B;
        #pragma unroll
        for (int i = 0; i < 2; i++) {
            int idx = i * 256 + t;
            int r = idx >> 2, seg = idx & 3;
            uint32_t so = (uint32_t)(r * PADK + seg * 8) * 2;
            size_t ga = (size_t)(m0 + r) * Kstride + kb + seg * 8;
            size_t gb = (size_t)(n0 + r) * Kstride + kb + seg * 8;
            cp16(base + OFF_AH + so, &Ahi[ga]);
            cp16(base + OFF_AL + so, &Alo[ga]);
            cp16(base + OFF_BH + so, &Bhi[gb]);
            cp16(base + OFF_BL + so, &Blo[gb]);
        }
        asm volatile("cp.async.commit_group;" ::: "memory");
    };

    issueChunk(0, 0);

    for (int c = 0; c < NC; c++) {
        const int buf = c & 1;
        if (c + 1 < NC) {
            issueChunk(c + 1, buf ^ 1);
            asm volatile("cp.async.wait_group 1;" ::: "memory");
        } else {
            asm volatile("cp.async.wait_group 0;" ::: "memory");
        }
        __syncthreads();

        const uint32_t base = sm + buf * BUF_B;
        #pragma unroll
        for (int kk = 0; kk < 32; kk += 16) {
            uint32_t a_h[2][4], a_l[2][4];
            #pragma unroll
            for (int at = 0; at < 2; at++) {
                int row = wm * 32 + at * 16 + (lid & 15);
                int col = kk + (lid >> 4) * 8;
                uint32_t ro = (uint32_t)(row * PADK + col) * 2;
                ldm_x4(a_h[at], base + OFF_AH + ro);
                ldm_x4(a_l[at], base + OFF_AL + ro);
            }
            uint32_t b_h[8][2], b_l[8][2];
            #pragma unroll
            for (int np = 0; np < 4; np++) {
                int quad = lid >> 3, qr = lid & 7;
                int nrow = wn * 64 + np * 16 + (quad >> 1) * 8 + qr;
                int col  = kk + (quad & 1) * 8;
                uint32_t ro = (uint32_t)(nrow * PADK + col) * 2;
                uint32_t r4[4];
                ldm_x4(r4, base + OFF_BH + ro);
                b_h[np*2][0] = r4[0]; b_h[np*2][1] = r4[1];
                b_h[np*2+1][0] = r4[2]; b_h[np*2+1][1] = r4[3];
                ldm_x4(r4, base + OFF_BL + ro);
                b_l[np*2][0] = r4[0]; b_l[np*2][1] = r4[1];
                b_l[np*2+1][0] = r4[2]; b_l[np*2+1][1] = r4[3];
            }
            #pragma unroll
            for (int at = 0; at < 2; at++)
                #pragma unroll
                for (int nt = 0; nt < 8; nt++) {
                    mma_bf16(acc[at][nt], a_h[at], b_h[nt]);
                    mma_bf16(acc[at][nt], a_h[at], b_l[nt]);
                    mma_bf16(acc[at][nt], a_l[at], b_h[nt]);
                }
        }
        __syncthreads();
    }

    // ---- epilogue ----
    #pragma unroll
    for (int at = 0; at < 2; at++) {
        #pragma unroll
        for (int nt = 0; nt < 8; nt++) {
            int col = n0 + wn * 64 + nt * 8 + (lid & 3) * 2;
            #pragma unroll
            for (int half = 0; half < 2; half++) {
                int row = m0 + wm * 32 + at * 16 + (lid >> 2) + half * 8;
                float v0 = acc[at][nt][half * 2 + 0];
                float v1 = acc[at][nt][half * 2 + 1];
                size_t gi = (size_t)row * N + col;
                if (bias) { v0 += bias[col]; v1 += bias[col + 1]; }
                if (act)  { v0 = gelu_f(v0); v1 = gelu_f(v1); }
                if (res)  { float2 r2 = *(const float2*)&res[gi]; v0 += r2.x; v1 += r2.y; }
                if (C) {
                    *(float2*)&C[gi] = make_float2(v0, v1);
                } else {
                    uint32_t uh, ul;
                    pack_split(v0, v1, uh, ul);
                    *(uint32_t*)&Chi[gi] = uh;
                    *(uint32_t*)&Clo[gi] = ul;
                }
            }
        }
    }
}

// ---------------- split-K reduction: out = sum(NS partials) + bias + res -----
template<int NS>
__global__ void ksum_kernel(const float* __restrict__ psum, const float* __restrict__ bias,
                            const float* __restrict__ res, float* __restrict__ out) {
    int i = blockIdx.x * 256 + threadIdx.x;       // float4 index, total NT*DD/4
    const float4* p0 = (const float4*)psum;
    float4 o = p0[i];
    #pragma unroll
    for (int s = 1; s < NS; s++) {
        float4 v = p0[i + (size_t)s * (NT*DD/4)];
        o.x += v.x; o.y += v.y; o.z += v.z; o.w += v.w;
    }
    int colb = (i & (DD/4 - 1));                  // float4 col within row
    float4 bv = ((const float4*)bias)[colb];
    float4 rv = ((const float4*)res)[i];
    o.x += bv.x + rv.x; o.y += bv.y + rv.y;
    o.z += bv.z + rv.z; o.w += bv.w + rv.w;
    ((float4*)out)[i] = o;
}

// ---------------- tensor-core flash attention (split-bf16, combined qkv) -----
#define AQS 40
#define AVS 72

__global__ __launch_bounds__(128)
void attn_mma(const __nv_bfloat16* __restrict__ qkvh, const __nv_bfloat16* __restrict__ qkvl,
              __nv_bfloat16* __restrict__ aoh, __nv_bfloat16* __restrict__ aol) {
    __shared__ __nv_bfloat16 Qh[128*AQS], Ql[128*AQS];
    __shared__ __nv_bfloat16 Kh[64*AQS],  Kl[64*AQS];
    __shared__ __nv_bfloat16 Vh[32*AVS],  Vl[32*AVS];
    const int h = blockIdx.y, b = blockIdx.z;
    const int t = threadIdx.x, w = t >> 5, lid = t & 31;
    const int q0 = blockIdx.x * 128;
    const int quad = lid >> 3, qr = lid & 7;
    const uint32_t sQh = smem_u32(Qh), sQl = smem_u32(Ql);
    const uint32_t sKh = smem_u32(Kh), sKl = smem_u32(Kl);
    const uint32_t sVh = smem_u32(Vh), sVl = smem_u32(Vl);
    const float scale = 0.17677669529663687f;   // 1/sqrt(32)

    #pragma unroll
    for (int i = 0; i < 4; i++) {
        int idx = i * 128 + t; int r = idx >> 2, seg = idx & 3;
        size_t g = ((size_t)(b * NTOK) + q0 + r) * QKVS + h * DHEAD + seg * 8;
        *(uint4*)(Qh + r * AQS + seg * 8) = *(const uint4*)&qkvh[g];
        *(uint4*)(Ql + r * AQS + seg * 8) = *(const uint4*)&qkvl[g];
    }

    float O[2][4][4];
    #pragma unroll
    for (int a1 = 0; a1 < 2; a1++)
        #pragma unroll
        for (int a2 = 0; a2 < 4; a2++)
            #pragma unroll
            for (int a3 = 0; a3 < 4; a3++) O[a1][a2][a3] = 0.f;
    float mrow[2][2] = {{-1e30f,-1e30f},{-1e30f,-1e30f}};
    float lrow[2][2] = {{0.f,0.f},{0.f,0.f}};

    for (int kt = 0; kt < NTOK; kt += 64) {
        #pragma unroll
        for (int i = 0; i < 2; i++) {
            int idx = i * 128 + t; int r = idx >> 2, seg = idx & 3;
            size_t g = ((size_t)(b * NTOK) + kt + r) * QKVS + 256 + h * DHEAD + seg * 8;
            cp16(sKh + (uint32_t)(r * AQS + seg * 8) * 2, &qkvh[g]);
            cp16(sKl + (uint32_t)(r * AQS + seg * 8) * 2, &qkvl[g]);
        }
        asm volatile("cp.async.commit_group;" ::: "memory");
        {
            int r2 = lid, seg = w;
            size_t g0 = ((size_t)(b * NTOK) + kt + 2 * r2) * QKVS + 512 + h * DHEAD + seg * 8;
            uint4 vh0 = *(const uint4*)&qkvh[g0];
            uint4 vh1 = *(const uint4*)&qkvh[g0 + QKVS];
            uint4 vl0 = *(const uint4*)&qkvl[g0];
            uint4 vl1 = *(const uint4*)&qkvl[g0 + QKVS];
            const __nv_bfloat16* h0 = (const __nv_bfloat16*)&vh0;
            const __nv_bfloat16* h1 = (const __nv_bfloat16*)&vh1;
            const __nv_bfloat16* l0 = (const __nv_bfloat16*)&vl0;
            const __nv_bfloat16* l1 = (const __nv_bfloat16*)&vl1;
            #pragma unroll
            for (int j = 0; j < 8; j++) {
                __nv_bfloat162 ph = __halves2bfloat162(h0[j], h1[j]);
                __nv_bfloat162 pl = __halves2bfloat162(l0[j], l1[j]);
                int off = (seg * 8 + j) * AVS + 2 * r2;
                *(uint32_t*)(Vh + off) = *(uint32_t*)&ph;
                *(uint32_t*)(Vl + off) = *(uint32_t*)&pl;
            }
        }
        asm volatile("cp.async.wait_group 0;" ::: "memory");
        __syncthreads();

        float S[2][8][4];
        #pragma unroll
        for (int a1 = 0; a1 < 2; a1++)
            #pragma unroll
            for (int a2 = 0; a2 < 8; a2++)
                #pragma unroll
                for (int a3 = 0; a3 < 4; a3++) S[a1][a2][a3] = 0.f;

        #pragma unroll
        for (int kk = 0; kk < 2; kk++) {
            uint32_t qa_h[2][4], qa_l[2][4];
            #pragma unroll
            for (int at = 0; at < 2; at++) {
                uint32_t ro = (uint32_t)((w * 32 + at * 16 + (lid & 15)) * AQS
                                         + kk * 16 + (lid >> 4) * 8) * 2;
                ldm_x4(qa_h[at], sQh + ro);
                ldm_x4(qa_l[at], sQl + ro);
            }
            uint32_t kb_h[8][2], kb_l[8][2];
            #pragma unroll
            for (int np = 0; np < 4; np++) {
                uint32_t ro = (uint32_t)((np * 16 + (quad >> 1) * 8 + qr) * AQS
                                         + kk * 16 + (quad & 1) * 8) * 2;
                uint32_t r4[4];
                ldm_x4(r4, sKh + ro);
                kb_h[np*2][0] = r4[0]; kb_h[np*2][1] = r4[1];
                kb_h[np*2+1][0] = r4[2]; kb_h[np*2+1][1] = r4[3];
                ldm_x4(r4, sKl + ro);
                kb_l[np*2][0] = r4[0]; kb_l[np*2][1] = r4[1];
                kb_l[np*2+1][0] = r4[2]; kb_l[np*2+1][1] = r4[3];
            }
            #pragma unroll
            for (int at = 0; at < 2; at++)
                #pragma unroll
                for (int nt = 0; nt < 8; nt++) {
                    mma_bf16(S[at][nt], qa_h[at], kb_h[nt]);
                    mma_bf16(S[at][nt], qa_h[at], kb_l[nt]);
                    mma_bf16(S[at][nt], qa_l[at], kb_h[nt]);
                }
        }

        #pragma unroll
        for (int at = 0; at < 2; at++) {
            float tm0 = -1e30f, tm1 = -1e30f;
            #pragma unroll
            for (int nt = 0; nt < 8; nt++) {
                S[at][nt][0] *= scale; S[at][nt][1] *= scale;
                S[at][nt][2] *= scale; S[at][nt][3] *= scale;
                tm0 = fmaxf(tm0, fmaxf(S[at][nt][0], S[at][nt][1]));
                tm1 = fmaxf(tm1, fmaxf(S[at][nt][2], S[at][nt][3]));
            }
            tm0 = fmaxf(tm0, __shfl_xor_sync(0xffffffffu, tm0, 1));
            tm0 = fmaxf(tm0, __shfl_xor_sync(0xffffffffu, tm0, 2));
            tm1 = fmaxf(tm1, __shfl_xor_sync(0xffffffffu, tm1, 1));
            tm1 = fmaxf(tm1, __shfl_xor_sync(0xffffffffu, tm1, 2));
            float m0n = fmaxf(mrow[at][0], tm0);
            float m1n = fmaxf(mrow[at][1], tm1);
            float c0 = __expf(mrow[at][0] - m0n);
            float c1 = __expf(mrow[at][1] - m1n);
            mrow[at][0] = m0n; mrow[at][1] = m1n;

            float ls0 = 0.f, ls1 = 0.f;
            uint32_t pah[4][4], pal[4][4];
            #pragma unroll
            for (int g = 0; g < 4; g++) {
                float p00 = __expf(S[at][2*g  ][0] - m0n);
                float p01 = __expf(S[at][2*g  ][1] - m0n);
                float p02 = __expf(S[at][2*g  ][2] - m1n);
                float p03 = __expf(S[at][2*g  ][3] - m1n);
                float p10 = __expf(S[at][2*g+1][0] - m0n);
                float p11 = __expf(S[at][2*g+1][1] - m0n);
                float p12 = __expf(S[at][2*g+1][2] - m1n);
                float p13 = __expf(S[at][2*g+1][3] - m1n);
                ls0 += p00 + p01 + p10 + p11;
                ls1 += p02 + p03 + p12 + p13;
                pack_split(p00, p01, pah[g][0], pal[g][0]);
                pack_split(p02, p03, pah[g][1], pal[g][1]);
                pack_split(p10, p11, pah[g][2], pal[g][2]);
                pack_split(p12, p13, pah[g][3], pal[g][3]);
            }
            ls0 += __shfl_xor_sync(0xffffffffu, ls0, 1);
            ls0 += __shfl_xor_sync(0xffffffffu, ls0, 2);
            ls1 += __shfl_xor_sync(0xffffffffu, ls1, 1);
            ls1 += __shfl_xor_sync(0xffffffffu, ls1, 2);
            lrow[at][0] = lrow[at][0] * c0 + ls0;
            lrow[at][1] = lrow[at][1] * c1 + ls1;
            #pragma unroll
            for (int vn = 0; vn < 4; vn++) {
                O[at][vn][0] *= c0; O[at][vn][1] *= c0;
                O[at][vn][2] *= c1; O[at][vn][3] *= c1;
            }
            #pragma unroll
            for (int g = 0; g < 4; g++) {
                uint32_t vb_h[4][2], vb_l[4][2];
                #pragma unroll
                for (int np = 0; np < 2; np++) {
                    uint32_t ro = (uint32_t)((np * 16 + (quad >> 1) * 8 + qr) * AVS
                                             + g * 16 + (quad & 1) * 8) * 2;
                    uint32_t r4[4];
                    ldm_x4(r4, sVh + ro);
                    vb_h[np*2][0] = r4[0]; vb_h[np*2][1] = r4[1];
                    vb_h[np*2+1][0] = r4[2]; vb_h[np*2+1][1] = r4[3];
                    ldm_x4(r4, sVl + ro);
                    vb_l[np*2][0] = r4[0]; vb_l[np*2][1] = r4[1];
                    vb_l[np*2+1][0] = r4[2]; vb_l[np*2+1][1] = r4[3];
                }
                #pragma unroll
                for (int vn = 0; vn < 4; vn++) {
                    mma_bf16(O[at][vn], pah[g], vb_h[vn]);
                    mma_bf16(O[at][vn], pah[g], vb_l[vn]);
                    mma_bf16(O[at][vn], pal[g], vb_h[vn]);
                }
            }
        }
        __syncthreads();
    }

    #pragma unroll
    for (int at = 0; at < 2; at++) {
        float i0 = 1.f / lrow[at][0];
        float i1 = 1.f / lrow[at][1];
        int r0 = q0 + w * 32 + at * 16 + (lid >> 2);
        #pragma unroll
        for (int vn = 0; vn < 4; vn++) {
            int col = h * DHEAD + vn * 8 + (lid & 3) * 2;
            size_t g0 = ((size_t)(b * NTOK) + r0) * DD + col;
            size_t g1 = g0 + (size_t)8 * DD;
            uint32_t uh, ul;
            pack_split(O[at][vn][0] * i0, O[at][vn][1] * i0, uh, ul);
            *(uint32_t*)&aoh[g0] = uh; *(uint32_t*)&aol[g0] = ul;
            pack_split(O[at][vn][2] * i1, O[at][vn][3] * i1, uh, ul);
            *(uint32_t*)&aoh[g1] = uh; *(uint32_t*)&aol[g1] = ul;
        }
    }
}

// ---------------- kmeans ----------------
__global__ void initcent_kernel(const float* __restrict__ x, float* __restrict__ cent) {
    cent[(size_t)blockIdx.x * DD + threadIdx.x] = x[(size_t)blockIdx.x * DD + threadIdx.x];
}

__global__ __launch_bounds__(128)
void assign_kernel(const float* __restrict__ x, const float* __restrict__ cent,
                   const float* __restrict__ xsq, const float* __restrict__ csq,
                   int* __restrict__ lab) {
    __shared__ float Xs[32][33];
    __shared__ float Cs[64][32];
    __shared__ float bd[32][4];
    __shared__ int   bc[32][4];
    const int t = threadIdx.x;
    const int p = t & 31, cg = t >> 5;
    const int p0 = blockIdx.x * 32;

    float dot[16];
    #pragma unroll
    for (int c = 0; c < 16; c++) dot[c] = 0.f;

    for (int dc = 0; dc < DD; dc += 32) {
        #pragma unroll
        for (int i = 0; i < 2; i++) {
            int idx = i * 128 + t;
            int r = idx >> 3, c4 = (idx & 7) * 4;
            float4 v = *(const float4*)&x[(size_t)(p0 + r) * DD + dc + c4];
            Xs[r][c4 + 0] = v.x; Xs[r][c4 + 1] = v.y;
            Xs[r][c4 + 2] = v.z; Xs[r][c4 + 3] = v.w;
        }
        #pragma unroll
        for (int i = 0; i < 4; i++) {
            int idx = i * 128 + t;
            int r = idx >> 3, c4 = (idx & 7) * 4;
            *(float4*)&Cs[r][c4] = *(const float4*)&cent[(size_t)r * DD + dc + c4];
        }
        __syncthreads();
        #pragma unroll 4
        for (int d = 0; d < 32; d++) {
            float xv = Xs[p][d];
            #pragma unroll
            for (int c = 0; c < 16; c++) dot[c] += xv * Cs[cg * 16 + c][d];
        }
        __syncthreads();
    }

    float xs = xsq[p0 + p];
    float best = 3.4e38f;
    int bl = 0;
    #pragma unroll
    for (int c = 0; c < 16; c++) {
        float dd = xs - 2.f * dot[c] + csq[cg * 16 + c];
        if (dd < best) { best = dd; bl = cg * 16 + c; }
    }
    bd[p][cg] = best; bc[p][cg] = bl;
    __syncthreads();
    if (t < 32) {
        float b2 = bd[t][0]; int l2 = bc[t][0];
        #pragma unroll
        for (int g = 1; g < 4; g++)
            if (bd[t][g] < b2) { b2 = bd[t][g]; l2 = bc[t][g]; }
        lab[p0 + t] = l2;
    }
}

__global__ __launch_bounds__(256)
void segsum1_kernel(const float* __restrict__ x, const int* __restrict__ lab,
                    float* __restrict__ part, float* __restrict__ pcnt) {
    const int pb = blockIdx.x;
    const int c0 = blockIdx.y * 16;
    const int t = threadIdx.x;
    __shared__ float ps[16][DD];
    __shared__ int labs[128];
    #pragma unroll
    for (int i = 0; i < 16; i++) ps[i][t] = 0.f;
    if (t < 128) labs[t] = lab[pb * 128 + t];
    __syncthreads();
    const int p0 = pb * 128;
    for (int i = 0; i < 128; i++) {
        int l = labs[i] - c0;
        if ((unsigned)l < 16u)
            ps[l][t] += x[(size_t)(p0 + i) * DD + t];
    }
    for (int c = 0; c < 16; c++)
        part[((size_t)pb * KC + c0 + c) * DD + t] = ps[c][t];
    if (t < 16) {
        int cnt = 0;
        for (int i = 0; i < 128; i++) cnt += (labs[i] == c0 + t);
        pcnt[pb * KC + c0 + t] = (float)cnt;
    }
}

__global__ __launch_bounds__(256)
void update_csq_kernel(const float* __restrict__ part, const float* __restrict__ pcnt,
                       float* __restrict__ cent, float* __restrict__ csq) {
    const int c = blockIdx.x, t = threadIdx.x;
    __shared__ float scnt;
    float acc = 0.f;
    #pragma unroll 8
    for (int b2 = 0; b2 < SB; b2++) acc += part[((size_t)b2 * KC + c) * DD + t];
    if (t == 0) {
        float cc = 0.f;
        #pragma unroll 8
        for (int b2 = 0; b2 < SB; b2++) cc += pcnt[b2 * KC + c];
        scnt = cc;
    }
    __syncthreads();
    float cv = cent[(size_t)c * DD + t];
    float nv = (scnt > 0.f) ? acc / fmaxf(scnt, 1.f) : cv;
    cent[(size_t)c * DD + t] = nv;
    float s = blockSum256(nv * nv);
    if (t == 0) csq[c] = s;
}

__global__ void cproj_kernel(const float* __restrict__ cent, const float* __restrict__ kW,
                             const float* __restrict__ kb, float* __restrict__ cpro) {
    __shared__ float cr[DD];
    int c = blockIdx.x, t = threadIdx.x;
    cr[t] = cent[(size_t)c * DD + t];
    __syncthreads();
    float acc = kb[t];
    for (int d = 0; d < DD; d++) acc += cr[d] * kW[(size_t)d * DD + t];
    cpro[(size_t)c * DD + t] = acc;
}

__global__ void gather_kernel(const float* __restrict__ cproj, const int* __restrict__ lab,
                              float* __restrict__ out) {
    int p = blockIdx.x, t = threadIdx.x;
    out[(size_t)p * DD + t] = cproj[(size_t)lab[p] * DD + t];
}

// ---------------- host orchestration ----------------
extern "C" void kernel_launch(void* const* d_in, const int* in_sizes, int n_in,
                              void* d_out, int out_size) {
    const float* x_in = (const float*)d_in[0];
    const float* ln1g = (const float*)d_in[1];
    const float* ln1b = (const float*)d_in[2];
    const float* Wq   = (const float*)d_in[3];
    const float* Wkv  = (const float*)d_in[4];
    const float* Wo   = (const float*)d_in[5];
    const float* bo   = (const float*)d_in[6];
    const float* ln2g = (const float*)d_in[7];
    const float* ln2b = (const float*)d_in[8];
    const float* W1   = (const float*)d_in[9];
    const float* b1   = (const float*)d_in[10];
    const float* W2   = (const float*)d_in[11];
    const float* b2   = (const float*)d_in[12];
    const float* kW   = (const float*)d_in[13];
    const float* kb   = (const float*)d_in[14];
    float* out = (float*)d_out;

    float *p_x, *p_xsq, *p_cent, *p_csq, *p_cpro, *p_part, *p_pcnt, *p_psum;
    __nv_bfloat16 *p_qkvh, *p_qkvl;
    __nv_bfloat16 *p_xnh, *p_xnl, *p_aoh, *p_aol, *p_hh, *p_hl, *p_wth, *p_wtl;
    int *p_lab;
    cudaGetSymbolAddress((void**)&p_x,    g_x);
    cudaGetSymbolAddress((void**)&p_qkvh, g_qkvh);
    cudaGetSymbolAddress((void**)&p_qkvl, g_qkvl);
    cudaGetSymbolAddress((void**)&p_xnh,  g_xnh);
    cudaGetSymbolAddress((void**)&p_xnl,  g_xnl);
    cudaGetSymbolAddress((void**)&p_aoh,  g_aoh);
    cudaGetSymbolAddress((void**)&p_aol,  g_aol);
    cudaGetSymbolAddress((void**)&p_hh,   g_hh);
    cudaGetSymbolAddress((void**)&p_hl,   g_hl);
    cudaGetSymbolAddress((void**)&p_wth,  g_wth);
    cudaGetSymbolAddress((void**)&p_wtl,  g_wtl);
    cudaGetSymbolAddress((void**)&p_psum, g_psum);
    cudaGetSymbolAddress((void**)&p_xsq,  g_xsq);
    cudaGetSymbolAddress((void**)&p_cent, g_cent);
    cudaGetSymbolAddress((void**)&p_csq,  g_csq);
    cudaGetSymbolAddress((void**)&p_lab,  g_lab);
    cudaGetSymbolAddress((void**)&p_cpro, g_cpro);
    cudaGetSymbolAddress((void**)&p_part, g_part);
    cudaGetSymbolAddress((void**)&p_pcnt, g_pcnt);

    cudaFuncSetAttribute(gemm_mma, cudaFuncAttributeMaxDynamicSharedMemorySize, GM_SMEM);

    dim3 tb32(32, 8);
    wsplit_kernel<<<dim3(8,  8, LL), tb32>>>(Wq,  p_wth + WQKV_OFF,         p_wtl + WQKV_OFF,         256, 256,  DD*DD,   WT_LAYER);
    wsplit_kernel<<<dim3(16, 8, LL), tb32>>>(Wkv, p_wth + WQKV_OFF + 65536, p_wtl + WQKV_OFF + 65536, 256, 512,  DD*2*DD, WT_LAYER);
    ln_kernel<<<NT / 8, 256>>>(x_in, ln1g, ln1b, p_xnh, p_xnl);
    wsplit_kernel<<<dim3(32, 8, LL), tb32>>>(W1,  p_wth + W1_OFF,           p_wtl + W1_OFF,           256, 1024, DD*MFF,  WT_LAYER);
    gemm_mma<<<dim3(6, 64), 256, GM_SMEM>>>(p_xnh, p_xnl, p_wth + WQKV_OFF, p_wtl + WQKV_OFF,
        nullptr, nullptr, nullptr, p_qkvh, p_qkvl, NT, QKVS, DD, DD, 0);
    wsplit_kernel<<<dim3(8,  8, LL), tb32>>>(Wo,  p_wth + WO_OFF,           p_wtl + WO_OFF,           256, 256,  DD*DD,   WT_LAYER);
    wsplit_kernel<<<dim3(8, 32, LL), tb32>>>(W2,  p_wth + W2_OFF,           p_wtl + W2_OFF,           1024, 256, MFF*DD,  WT_LAYER);

    for (int l = 0; l < LL; l++) {
        size_t wb = (size_t)l * WT_LAYER;
        const __nv_bfloat16* wqkvh = p_wth + wb + WQKV_OFF, *wqkvl = p_wtl + wb + WQKV_OFF;
        const __nv_bfloat16* woh   = p_wth + wb + WO_OFF,   *wol   = p_wtl + wb + WO_OFF;
        const __nv_bfloat16* w1h   = p_wth + wb + W1_OFF,   *w1l   = p_wtl + wb + W1_OFF;
        const __nv_bfloat16* w2h   = p_wth + wb + W2_OFF,   *w2l   = p_wtl + wb + W2_OFF;
        const float* xsrc = (l == 0) ? x_in : p_x;

        if (l > 0) {
            ln_kernel<<<NT / 8, 256>>>(xsrc, ln1g + l * DD, ln1b + l * DD, p_xnh, p_xnl);
            gemm_mma<<<dim3(6, 64), 256, GM_SMEM>>>(p_xnh, p_xnl, wqkvh, wqkvl,
                nullptr, nullptr, nullptr, p_qkvh, p_qkvl, NT, QKVS, DD, DD, 0);
        }
        // attention -> split ao
        attn_mma<<<dim3(NTOK / 128, HH, BB), 128>>>(p_qkvh, p_qkvl, p_aoh, p_aol);
        // out proj + bias + residual (into x) — fused epilogue
        gemm_mma<<<dim3(2, 64), 256, GM_SMEM>>>(p_aoh, p_aol, woh, wol,
            bo + l * DD, xsrc, p_x, nullptr, nullptr, NT, DD, DD, DD, 0);
        // ln2 -> split xn
        ln_kernel<<<NT / 8, 256>>>(p_x, ln2g + l * DD, ln2b + l * DD, p_xnh, p_xnl);
        // ffn up + gelu -> split h
        gemm_mma<<<dim3(8, 64), 256, GM_SMEM>>>(p_xnh, p_xnl, w1h, w1l,
            b1 + l * MFF, nullptr, nullptr, p_hh, p_hl, NT, MFF, DD, DD, 1);
        // ffn down: split-K=4 partials, then deterministic reduction + bias + res
        gemm_mma<<<dim3(2, 64, NSPLIT), 256, GM_SMEM>>>(p_hh, p_hl, w2h, w2l,
            nullptr, nullptr, p_psum, nullptr, nullptr, NT, DD, MFF / NSPLIT, MFF, 0);
        ksum_kernel<NSPLIT><<<NT * DD / 4 / 256, 256>>>(p_psum, b2 + l * DD, p_x, p_x);
    }

    // ---- kmeans (fp32, deterministic) ----
    initcent_kernel<<<KC, 256>>>(p_x, p_cent);
    rowsumsq_kernel<<<NT / 8, 256>>>(p_x, p_xsq);
    rowsumsq_kernel<<<KC / 8, 256>>>(p_cent, p_csq);

    for (int it = 0; it < KM_IT; it++) {
        assign_kernel<<<NT / 32, 128>>>(p_x, p_cent, p_xsq, p_csq, p_lab);
        segsum1_kernel<<<dim3(SB, 4), 256>>>(p_x, p_lab, p_part, p_pcnt);
        update_csq_kernel<<<KC, 256>>>(p_part, p_pcnt, p_cent, p_csq);
    }
    assign_kernel<<<NT / 32, 128>>>(p_x, p_cent, p_xsq, p_csq, p_lab);

    cproj_kernel<<<KC, 256>>>(p_cent, kW, kb, p_cpro);
    gather_kernel<<<NT, 256>>>(p_cpro, p_lab, out);
}

// round 16
// speedup vs baseline: 1.0299x; 1.0299x over previous
#include <cuda_runtime.h>
#include <cuda_bf16.h>
#include <math.h>
#include <stdint.h>

// ---------------- problem constants ----------------
#define BB     8
#define NTOK   1024
#define DD     256
#define LL     4
#define MFF    1024
#define HH     8
#define DHEAD  32
#define NT     (BB*NTOK)      // 8192 tokens
#define KC     64             // clusters
#define KM_IT  10
#define SB     64             // segsum point-blocks (128 points each)
#define QKVS   768            // combined qkv row stride
#define NSPLIT 4              // split-K factor for ffn-down

// weight-transpose scratch offsets (elements, per layer base = l*786432)
#define WT_LAYER 786432
#define WQKV_OFF 0
#define WO_OFF   196608
#define W1_OFF   262144
#define W2_OFF   524288

// ---------------- scratch (static device globals; no allocation allowed) ----
__device__ float g_x   [NT*DD];          // running residual stream (fp32)
__device__ __nv_bfloat16 g_qkvh[NT*QKVS];
__device__ __nv_bfloat16 g_qkvl[NT*QKVS];
__device__ __nv_bfloat16 g_vth [BB*HH*DHEAD*NTOK];  // V^T [b][h][dim][key] hi
__device__ __nv_bfloat16 g_vtl [BB*HH*DHEAD*NTOK];  // V^T lo
__device__ __nv_bfloat16 g_xnh[NT*DD];
__device__ __nv_bfloat16 g_xnl[NT*DD];
__device__ __nv_bfloat16 g_aoh[NT*DD];
__device__ __nv_bfloat16 g_aol[NT*DD];
__device__ __nv_bfloat16 g_hh [NT*MFF];
__device__ __nv_bfloat16 g_hl [NT*MFF];
__device__ __nv_bfloat16 g_wth[LL*WT_LAYER];
__device__ __nv_bfloat16 g_wtl[LL*WT_LAYER];
__device__ float g_psum[NSPLIT*NT*DD];   // split-K partials (32 MB)
__device__ float g_xsq [NT];
__device__ float g_cent[KC*DD];
__device__ float g_csq [KC];
__device__ int   g_lab [NT];
__device__ float g_cpro[KC*DD];
__device__ float g_part[SB*KC*DD];
__device__ float g_pcnt[SB*KC];

// ---------------- small helpers ----------------
__device__ __forceinline__ float gelu_f(float x) {
    return 0.5f * x * (1.0f + erff(x * 0.7071067811865476f));
}
__device__ __forceinline__ float warpSum(float v) {
    #pragma unroll
    for (int o = 16; o > 0; o >>= 1) v += __shfl_xor_sync(0xffffffffu, v, o);
    return v;
}
__device__ __forceinline__ float blockSum256(float v) {
    __shared__ float red[8];
    int t = threadIdx.x;
    v = warpSum(v);
    if ((t & 31) == 0) red[t >> 5] = v;
    __syncthreads();
    float s = 0.f;
    if (t == 0) {
        #pragma unroll
        for (int i = 0; i < 8; i++) s += red[i];
        red[0] = s;
    }
    __syncthreads();
    s = red[0];
    __syncthreads();
    return s;
}
__device__ __forceinline__ void splitf(float v, __nv_bfloat16& h, __nv_bfloat16& l) {
    h = __float2bfloat16(v);
    l = __float2bfloat16(v - __bfloat162float(h));
}
__device__ __forceinline__ void pack_split(float a, float b, uint32_t& hi, uint32_t& lo) {
    __nv_bfloat16 ah, al, bh, bl;
    splitf(a, ah, al); splitf(b, bh, bl);
    __nv_bfloat162 h2 = __halves2bfloat162(ah, bh);
    __nv_bfloat162 l2 = __halves2bfloat162(al, bl);
    hi = *(uint32_t*)&h2; lo = *(uint32_t*)&l2;
}
__device__ __forceinline__ uint32_t smem_u32(const void* p) {
    uint32_t a;
    asm("{ .reg .u64 t; cvta.to.shared.u64 t, %1; cvt.u32.u64 %0, t; }" : "=r"(a) : "l"(p));
    return a;
}

// ---------------- mma.sync helpers ----------------
__device__ __forceinline__ void ldm_x4(uint32_t* r, uint32_t addr) {
    asm volatile("ldmatrix.sync.aligned.m8n8.x4.shared.b16 {%0,%1,%2,%3}, [%4];"
                 : "=r"(r[0]), "=r"(r[1]), "=r"(r[2]), "=r"(r[3]) : "r"(addr));
}
__device__ __forceinline__ void mma_bf16(float* c, const uint32_t* a, const uint32_t* b) {
    asm volatile(
        "mma.sync.aligned.m16n8k16.row.col.f32.bf16.bf16.f32 "
        "{%0,%1,%2,%3}, {%4,%5,%6,%7}, {%8,%9}, {%0,%1,%2,%3};"
        : "+f"(c[0]), "+f"(c[1]), "+f"(c[2]), "+f"(c[3])
        : "r"(a[0]), "r"(a[1]), "r"(a[2]), "r"(a[3]), "r"(b[0]), "r"(b[1]));
}
__device__ __forceinline__ void cp16(uint32_t dst, const void* src) {
    asm volatile("cp.async.cg.shared.global [%0], [%1], 16;"
                 :: "r"(dst), "l"(src) : "memory");
}

// ---------------- layernorm: one WARP per row; emits split-bf16 --------------
__global__ void ln_kernel(const float* __restrict__ x, const float* __restrict__ g,
                          const float* __restrict__ b,
                          __nv_bfloat16* __restrict__ oh, __nv_bfloat16* __restrict__ ol) {
    int row  = (blockIdx.x * blockDim.x + threadIdx.x) >> 5;
    int lane = threadIdx.x & 31;
    const float* xp = x + (size_t)row * DD;
    float4 a = *(const float4*)&xp[lane * 4];
    float4 c = *(const float4*)&xp[128 + lane * 4];
    float s = a.x + a.y + a.z + a.w + c.x + c.y + c.z + c.w;
    float mean = warpSum(s) * (1.0f / DD);
    float4 da = make_float4(a.x - mean, a.y - mean, a.z - mean, a.w - mean);
    float4 dc = make_float4(c.x - mean, c.y - mean, c.z - mean, c.w - mean);
    float v = da.x*da.x + da.y*da.y + da.z*da.z + da.w*da.w
            + dc.x*dc.x + dc.y*dc.y + dc.z*dc.z + dc.w*dc.w;
    float rs = rsqrtf(warpSum(v) * (1.0f / DD) + 1e-5f);
    float4 g0 = *(const float4*)&g[lane * 4];
    float4 g1 = *(const float4*)&g[128 + lane * 4];
    float4 b0 = *(const float4*)&b[lane * 4];
    float4 b1 = *(const float4*)&b[128 + lane * 4];
    float o0[4] = { da.x*rs*g0.x + b0.x, da.y*rs*g0.y + b0.y,
                    da.z*rs*g0.z + b0.z, da.w*rs*g0.w + b0.w };
    float o1[4] = { dc.x*rs*g1.x + b1.x, dc.y*rs*g1.y + b1.y,
                    dc.z*rs*g1.z + b1.z, dc.w*rs*g1.w + b1.w };
    size_t base = (size_t)row * DD;
    #pragma unroll
    for (int j = 0; j < 2; j++) {
        uint32_t uh, ul;
        pack_split(o0[j*2+0], o0[j*2+1], uh, ul);
        *(uint32_t*)&oh[base + lane*4 + j*2] = uh;
        *(uint32_t*)&ol[base + lane*4 + j*2] = ul;
        pack_split(o1[j*2+0], o1[j*2+1], uh, ul);
        *(uint32_t*)&oh[base + 128 + lane*4 + j*2] = uh;
        *(uint32_t*)&ol[base + 128 + lane*4 + j*2] = ul;
    }
}

// ---------------- row sum-of-squares ----------------
__global__ void rowsumsq_kernel(const float* __restrict__ x, float* __restrict__ out) {
    int row  = (blockIdx.x * blockDim.x + threadIdx.x) >> 5;
    int lane = threadIdx.x & 31;
    const float* xp = x + (size_t)row * DD;
    float4 a = *(const float4*)&xp[lane * 4];
    float4 c = *(const float4*)&xp[128 + lane * 4];
    float s = a.x*a.x + a.y*a.y + a.z*a.z + a.w*a.w
            + c.x*c.x + c.y*c.y + c.z*c.z + c.w*c.w;
    s = warpSum(s);
    if (lane == 0) out[row] = s;
}

// -------- weight transpose + bf16 split (batched over layers) ----------------
__global__ void wsplit_kernel(const float* __restrict__ W,
                              __nv_bfloat16* __restrict__ oh, __nv_bfloat16* __restrict__ ol,
                              int K, int N, int strideW, int strideO) {
    __shared__ float tile[32][33];
    const int l = blockIdx.z;
    const float* Wl = W + (size_t)l * strideW;
    __nv_bfloat16* ohl = oh + (size_t)l * strideO;
    __nv_bfloat16* oll = ol + (size_t)l * strideO;
    int k0 = blockIdx.y * 32, n0 = blockIdx.x * 32;
    int tx = threadIdx.x, ty = threadIdx.y;   // 32 x 8
    #pragma unroll
    for (int j = 0; j < 4; j++)
        tile[ty + j*8][tx] = Wl[(size_t)(k0 + ty + j*8) * N + n0 + tx];
    __syncthreads();
    #pragma unroll
    for (int j = 0; j < 4; j++) {
        int n = ty + j*8;
        float v = tile[tx][n];
        size_t idx = (size_t)(n0 + n) * K + k0 + tx;
        __nv_bfloat16 h, l2; splitf(v, h, l2);
        ohl[idx] = h; oll[idx] = l2;
    }
}

// -------- V transpose: qkv V-part -> Vt [b][h][dim][key] (hi/lo) -------------
__global__ __launch_bounds__(256)
void vtrans_kernel(const __nv_bfloat16* __restrict__ qkvh, const __nv_bfloat16* __restrict__ qkvl,
                   __nv_bfloat16* __restrict__ vth, __nv_bfloat16* __restrict__ vtl) {
    __shared__ __nv_bfloat16 Sh[256*40];
    __shared__ __nv_bfloat16 Sl[256*40];
    const int t = threadIdx.x;
    const int kb = blockIdx.x * 256;
    const int h = blockIdx.y, b = blockIdx.z;
    {
        size_t g = ((size_t)(b * NTOK) + kb + t) * QKVS + 512 + h * DHEAD;
        #pragma unroll
        for (int s = 0; s < 4; s++) {
            *(uint4*)&Sh[t * 40 + s * 8] = *(const uint4*)&qkvh[g + s * 8];
            *(uint4*)&Sl[t * 40 + s * 8] = *(const uint4*)&qkvl[g + s * 8];
        }
    }
    __syncthreads();
    __nv_bfloat16* oh = vth + ((size_t)(b * HH + h) * DHEAD) * NTOK + kb;
    __nv_bfloat16* ol = vtl + ((size_t)(b * HH + h) * DHEAD) * NTOK + kb;
    #pragma unroll
    for (int i = 0; i < 4; i++) {
        int idx = i * 256 + t;            // 0..1023
        int d = idx >> 5, c8 = idx & 31;  // dim 0..31, key-chunk 0..31
        __nv_bfloat16 th[8], tl[8];
        #pragma unroll
        for (int j = 0; j < 8; j++) {
            th[j] = Sh[(c8 * 8 + j) * 40 + d];
            tl[j] = Sl[(c8 * 8 + j) * 40 + d];
        }
        *(uint4*)&oh[(size_t)d * NTOK + c8 * 8] = *(uint4*)th;
        *(uint4*)&ol[(size_t)d * NTOK + c8 * 8] = *(uint4*)tl;
    }
}

// ---------------- split-bf16 GEMM on HMMA (128x128) --------------------------
#define PADK   40
#define ARR_B  (128*PADK*2)
#define OFF_AH 0
#define OFF_AL (1*ARR_B)
#define OFF_BH (2*ARR_B)
#define OFF_BL (3*ARR_B)
#define BUF_B  (4*ARR_B)
#define GM_SMEM (2*BUF_B)               // 81920

__global__ __launch_bounds__(256)
void gemm_mma(const __nv_bfloat16* __restrict__ Ahi, const __nv_bfloat16* __restrict__ Alo,
              const __nv_bfloat16* __restrict__ Bhi, const __nv_bfloat16* __restrict__ Blo,
              const float* __restrict__ bias, const float* __restrict__ res,
              float* __restrict__ C,
              __nv_bfloat16* __restrict__ Chi, __nv_bfloat16* __restrict__ Clo,
              int M, int N, int K, int Kstride, int act) {
    extern __shared__ char smem[];
    const uint32_t sm = smem_u32(smem);
    const int m0 = blockIdx.y * 128;
    const int n0 = blockIdx.x * 128;
    const int koff = blockIdx.z * K;
    const int t = threadIdx.x;
    const int wid = t >> 5, lid = t & 31;
    const int wm = wid & 3;
    const int wn = wid >> 2;
    const int NC = K >> 5;
    if (C) C += (size_t)blockIdx.z * ((size_t)M * N);

    float acc[2][8][4];
    #pragma unroll
    for (int i = 0; i < 2; i++)
        #pragma unroll
        for (int j = 0; j < 8; j++)
            #pragma unroll
            for (int q = 0; q < 4; q++) acc[i][j][q] = 0.f;

    auto issueChunk = [&](int c, int buf) {
        const int kb = koff + c * 32;
        const uint32_t base = sm + buf * BUF_B;
        #pragma unroll
        for (int i = 0; i < 2; i++) {
            int idx = i * 256 + t;
            int r = idx >> 2, seg = idx & 3;
            uint32_t so = (uint32_t)(r * PADK + seg * 8) * 2;
            size_t ga = (size_t)(m0 + r) * Kstride + kb + seg * 8;
            size_t gb = (size_t)(n0 + r) * Kstride + kb + seg * 8;
            cp16(base + OFF_AH + so, &Ahi[ga]);
            cp16(base + OFF_AL + so, &Alo[ga]);
            cp16(base + OFF_BH + so, &Bhi[gb]);
            cp16(base + OFF_BL + so, &Blo[gb]);
        }
        asm volatile("cp.async.commit_group;" ::: "memory");
    };

    issueChunk(0, 0);

    for (int c = 0; c < NC; c++) {
        const int buf = c & 1;
        if (c + 1 < NC) {
            issueChunk(c + 1, buf ^ 1);
            asm volatile("cp.async.wait_group 1;" ::: "memory");
        } else {
            asm volatile("cp.async.wait_group 0;" ::: "memory");
        }
        __syncthreads();

        const uint32_t base = sm + buf * BUF_B;
        #pragma unroll
        for (int kk = 0; kk < 32; kk += 16) {
            uint32_t a_h[2][4], a_l[2][4];
            #pragma unroll
            for (int at = 0; at < 2; at++) {
                int row = wm * 32 + at * 16 + (lid & 15);
                int col = kk + (lid >> 4) * 8;
                uint32_t ro = (uint32_t)(row * PADK + col) * 2;
                ldm_x4(a_h[at], base + OFF_AH + ro);
                ldm_x4(a_l[at], base + OFF_AL + ro);
            }
            uint32_t b_h[8][2], b_l[8][2];
            #pragma unroll
            for (int np = 0; np < 4; np++) {
                int quad = lid >> 3, qr = lid & 7;
                int nrow = wn * 64 + np * 16 + (quad >> 1) * 8 + qr;
                int col  = kk + (quad & 1) * 8;
                uint32_t ro = (uint32_t)(nrow * PADK + col) * 2;
                uint32_t r4[4];
                ldm_x4(r4, base + OFF_BH + ro);
                b_h[np*2][0] = r4[0]; b_h[np*2][1] = r4[1];
                b_h[np*2+1][0] = r4[2]; b_h[np*2+1][1] = r4[3];
                ldm_x4(r4, base + OFF_BL + ro);
                b_l[np*2][0] = r4[0]; b_l[np*2][1] = r4[1];
                b_l[np*2+1][0] = r4[2]; b_l[np*2+1][1] = r4[3];
            }
            #pragma unroll
            for (int at = 0; at < 2; at++)
                #pragma unroll
                for (int nt = 0; nt < 8; nt++) {
                    mma_bf16(acc[at][nt], a_h[at], b_h[nt]);
                    mma_bf16(acc[at][nt], a_h[at], b_l[nt]);
                    mma_bf16(acc[at][nt], a_l[at], b_h[nt]);
                }
        }
        __syncthreads();
    }

    // ---- epilogue ----
    #pragma unroll
    for (int at = 0; at < 2; at++) {
        #pragma unroll
        for (int nt = 0; nt < 8; nt++) {
            int col = n0 + wn * 64 + nt * 8 + (lid & 3) * 2;
            #pragma unroll
            for (int half = 0; half < 2; half++) {
                int row = m0 + wm * 32 + at * 16 + (lid >> 2) + half * 8;
                float v0 = acc[at][nt][half * 2 + 0];
                float v1 = acc[at][nt][half * 2 + 1];
                size_t gi = (size_t)row * N + col;
                if (bias) { v0 += bias[col]; v1 += bias[col + 1]; }
                if (act)  { v0 = gelu_f(v0); v1 = gelu_f(v1); }
                if (res)  { float2 r2 = *(const float2*)&res[gi]; v0 += r2.x; v1 += r2.y; }
                if (C) {
                    *(float2*)&C[gi] = make_float2(v0, v1);
                } else {
                    uint32_t uh, ul;
                    pack_split(v0, v1, uh, ul);
                    *(uint32_t*)&Chi[gi] = uh;
                    *(uint32_t*)&Clo[gi] = ul;
                }
            }
        }
    }
}

// ---------------- split-K reduction: out = sum(NS partials) + bias + res -----
template<int NS>
__global__ void ksum_kernel(const float* __restrict__ psum, const float* __restrict__ bias,
                            const float* __restrict__ res, float* __restrict__ out) {
    int i = blockIdx.x * 256 + threadIdx.x;       // float4 index, total NT*DD/4
    const float4* p0 = (const float4*)psum;
    float4 o = p0[i];
    #pragma unroll
    for (int s = 1; s < NS; s++) {
        float4 v = p0[i + (size_t)s * (NT*DD/4)];
        o.x += v.x; o.y += v.y; o.z += v.z; o.w += v.w;
    }
    int colb = (i & (DD/4 - 1));                  // float4 col within row
    float4 bv = ((const float4*)bias)[colb];
    float4 rv = ((const float4*)res)[i];
    o.x += bv.x + rv.x; o.y += bv.y + rv.y;
    o.z += bv.z + rv.z; o.w += bv.w + rv.w;
    ((float4*)out)[i] = o;
}

// ---------------- tensor-core flash attention ---------------------------------
// Double-buffered K/V tiles via cp.async; V pre-transposed by vtrans_kernel.
#define AQS 40
#define AVS 72
#define A_QH 0
#define A_QL 10240
#define A_KBASE 20480
#define A_KL    5120
#define A_KSTRIDE 10240
#define A_VBASE 40960
#define A_VL    4608
#define A_VSTRIDE 9216
#define A_SMEM  59392

__global__ __launch_bounds__(128)
void attn_mma(const __nv_bfloat16* __restrict__ qkvh, const __nv_bfloat16* __restrict__ qkvl,
              const __nv_bfloat16* __restrict__ vth, const __nv_bfloat16* __restrict__ vtl,
              __nv_bfloat16* __restrict__ aoh, __nv_bfloat16* __restrict__ aol) {
    extern __shared__ char asmem[];
    const uint32_t sb = smem_u32(asmem);
    const int h = blockIdx.y, b = blockIdx.z;
    const int t = threadIdx.x, w = t >> 5, lid = t & 31;
    const int q0 = blockIdx.x * 128;
    const int quad = lid >> 3, qr = lid & 7;
    const float scale = 0.17677669529663687f;   // 1/sqrt(32)
    const __nv_bfloat16* vtbh = vth + ((size_t)(b * HH + h) * DHEAD) * NTOK;
    const __nv_bfloat16* vtbl = vtl + ((size_t)(b * HH + h) * DHEAD) * NTOK;

    // ---- stage Q tile (128 x 32) ----
    #pragma unroll
    for (int i = 0; i < 4; i++) {
        int idx = i * 128 + t; int r = idx >> 2, seg = idx & 3;
        size_t g = ((size_t)(b * NTOK) + q0 + r) * QKVS + h * DHEAD + seg * 8;
        *(uint4*)(asmem + A_QH + (uint32_t)(r * AQS + seg * 8) * 2) = *(const uint4*)&qkvh[g];
        *(uint4*)(asmem + A_QL + (uint32_t)(r * AQS + seg * 8) * 2) = *(const uint4*)&qkvl[g];
    }

    auto issueTile = [&](int kt, int buf) {
        const uint32_t kb = sb + A_KBASE + buf * A_KSTRIDE;
        #pragma unroll
        for (int i = 0; i < 2; i++) {
            int idx = i * 128 + t; int r = idx >> 2, seg = idx & 3;
            size_t g = ((size_t)(b * NTOK) + kt + r) * QKVS + 256 + h * DHEAD + seg * 8;
            uint32_t so = (uint32_t)(r * AQS + seg * 8) * 2;
            cp16(kb + so, &qkvh[g]);
            cp16(kb + A_KL + so, &qkvl[g]);
        }
        const uint32_t vb = sb + A_VBASE + buf * A_VSTRIDE;
        #pragma unroll
        for (int i = 0; i < 2; i++) {
            int idx = i * 128 + t;               // 0..255
            int d = idx >> 3, ch = idx & 7;      // dim 0..31, key-chunk 0..7
            uint32_t so = (uint32_t)(d * AVS + ch * 8) * 2;
            cp16(vb + so, vtbh + (size_t)d * NTOK + kt + ch * 8);
            cp16(vb + A_VL + so, vtbl + (size_t)d * NTOK + kt + ch * 8);
        }
        asm volatile("cp.async.commit_group;" ::: "memory");
    };

    float O[2][4][4];
    #pragma unroll
    for (int a1 = 0; a1 < 2; a1++)
        #pragma unroll
        for (int a2 = 0; a2 < 4; a2++)
            #pragma unroll
            for (int a3 = 0; a3 < 4; a3++) O[a1][a2][a3] = 0.f;
    float mrow[2][2] = {{-1e30f,-1e30f},{-1e30f,-1e30f}};
    float lrow[2][2] = {{0.f,0.f},{0.f,0.f}};

    issueTile(0, 0);

    for (int it = 0; it < NTOK / 64; it++) {
        const int buf = it & 1;
        if (it + 1 < NTOK / 64) {
            issueTile((it + 1) * 64, buf ^ 1);
            asm volatile("cp.async.wait_group 1;" ::: "memory");
        } else {
            asm volatile("cp.async.wait_group 0;" ::: "memory");
        }
        __syncthreads();

        const uint32_t sQh = sb + A_QH, sQl = sb + A_QL;
        const uint32_t sKh = sb + A_KBASE + buf * A_KSTRIDE, sKl = sKh + A_KL;
        const uint32_t sVh = sb + A_VBASE + buf * A_VSTRIDE, sVl = sVh + A_VL;

        float S[2][8][4];
        #pragma unroll
        for (int a1 = 0; a1 < 2; a1++)
            #pragma unroll
            for (int a2 = 0; a2 < 8; a2++)
                #pragma unroll
                for (int a3 = 0; a3 < 4; a3++) S[a1][a2][a3] = 0.f;

        #pragma unroll
        for (int kk = 0; kk < 2; kk++) {
            uint32_t qa_h[2][4], qa_l[2][4];
            #pragma unroll
            for (int at = 0; at < 2; at++) {
                uint32_t ro = (uint32_t)((w * 32 + at * 16 + (lid & 15)) * AQS
                                         + kk * 16 + (lid >> 4) * 8) * 2;
                ldm_x4(qa_h[at], sQh + ro);
                ldm_x4(qa_l[at], sQl + ro);
            }
            uint32_t kb_h[8][2], kb_l[8][2];
            #pragma unroll
            for (int np = 0; np < 4; np++) {
                uint32_t ro = (uint32_t)((np * 16 + (quad >> 1) * 8 + qr) * AQS
                                         + kk * 16 + (quad & 1) * 8) * 2;
                uint32_t r4[4];
                ldm_x4(r4, sKh + ro);
                kb_h[np*2][0] = r4[0]; kb_h[np*2][1] = r4[1];
                kb_h[np*2+1][0] = r4[2]; kb_h[np*2+1][1] = r4[3];
                ldm_x4(r4, sKl + ro);
                kb_l[np*2][0] = r4[0]; kb_l[np*2][1] = r4[1];
                kb_l[np*2+1][0] = r4[2]; kb_l[np*2+1][1] = r4[3];
            }
            #pragma unroll
            for (int at = 0; at < 2; at++)
                #pragma unroll
                for (int nt = 0; nt < 8; nt++) {
                    mma_bf16(S[at][nt], qa_h[at], kb_h[nt]);
                    mma_bf16(S[at][nt], qa_h[at], kb_l[nt]);
                    mma_bf16(S[at][nt], qa_l[at], kb_h[nt]);
                }
        }

        #pragma unroll
        for (int at = 0; at < 2; at++) {
            float tm0 = -1e30f, tm1 = -1e30f;
            #pragma unroll
            for (int nt = 0; nt < 8; nt++) {
                S[at][nt][0] *= scale; S[at][nt][1] *= scale;
                S[at][nt][2] *= scale; S[at][nt][3] *= scale;
                tm0 = fmaxf(tm0, fmaxf(S[at][nt][0], S[at][nt][1]));
                tm1 = fmaxf(tm1, fmaxf(S[at][nt][2], S[at][nt][3]));
            }
            tm0 = fmaxf(tm0, __shfl_xor_sync(0xffffffffu, tm0, 1));
            tm0 = fmaxf(tm0, __shfl_xor_sync(0xffffffffu, tm0, 2));
            tm1 = fmaxf(tm1, __shfl_xor_sync(0xffffffffu, tm1, 1));
            tm1 = fmaxf(tm1, __shfl_xor_sync(0xffffffffu, tm1, 2));
            float m0n = fmaxf(mrow[at][0], tm0);
            float m1n = fmaxf(mrow[at][1], tm1);
            float c0 = __expf(mrow[at][0] - m0n);
            float c1 = __expf(mrow[at][1] - m1n);
            mrow[at][0] = m0n; mrow[at][1] = m1n;

            float ls0 = 0.f, ls1 = 0.f;
            uint32_t pah[4][4], pal[4][4];
            #pragma unroll
            for (int g = 0; g < 4; g++) {
                float p00 = __expf(S[at][2*g  ][0] - m0n);
                float p01 = __expf(S[at][2*g  ][1] - m0n);
                float p02 = __expf(S[at][2*g  ][2] - m1n);
                float p03 = __expf(S[at][2*g  ][3] - m1n);
                float p10 = __expf(S[at][2*g+1][0] - m0n);
                float p11 = __expf(S[at][2*g+1][1] - m0n);
                float p12 = __expf(S[at][2*g+1][2] - m1n);
                float p13 = __expf(S[at][2*g+1][3] - m1n);
                ls0 += p00 + p01 + p10 + p11;
                ls1 += p02 + p03 + p12 + p13;
                pack_split(p00, p01, pah[g][0], pal[g][0]);
                pack_split(p02, p03, pah[g][1], pal[g][1]);
                pack_split(p10, p11, pah[g][2], pal[g][2]);
                pack_split(p12, p13, pah[g][3], pal[g][3]);
            }
            ls0 += __shfl_xor_sync(0xffffffffu, ls0, 1);
            ls0 += __shfl_xor_sync(0xffffffffu, ls0, 2);
            ls1 += __shfl_xor_sync(0xffffffffu, ls1, 1);
            ls1 += __shfl_xor_sync(0xffffffffu, ls1, 2);
            lrow[at][0] = lrow[at][0] * c0 + ls0;
            lrow[at][1] = lrow[at][1] * c1 + ls1;
            #pragma unroll
            for (int vn = 0; vn < 4; vn++) {
                O[at][vn][0] *= c0; O[at][vn][1] *= c0;
                O[at][vn][2] *= c1; O[at][vn][3] *= c1;
            }
            #pragma unroll
            for (int g = 0; g < 4; g++) {
                uint32_t vb_h[4][2], vb_l[4][2];
                #pragma unroll
                for (int np = 0; np < 2; np++) {
                    uint32_t ro = (uint32_t)((np * 16 + (quad >> 1) * 8 + qr) * AVS
                                             + g * 16 + (quad & 1) * 8) * 2;
                    uint32_t r4[4];
                    ldm_x4(r4, sVh + ro);
                    vb_h[np*2][0] = r4[0]; vb_h[np*2][1] = r4[1];
                    vb_h[np*2+1][0] = r4[2]; vb_h[np*2+1][1] = r4[3];
                    ldm_x4(r4, sVl + ro);
                    vb_l[np*2][0] = r4[0]; vb_l[np*2][1] = r4[1];
                    vb_l[np*2+1][0] = r4[2]; vb_l[np*2+1][1] = r4[3];
                }
                #pragma unroll
                for (int vn = 0; vn < 4; vn++) {
                    mma_bf16(O[at][vn], pah[g], vb_h[vn]);
                    mma_bf16(O[at][vn], pah[g], vb_l[vn]);
                    mma_bf16(O[at][vn], pal[g], vb_h[vn]);
                }
            }
        }
        __syncthreads();
    }

    #pragma unroll
    for (int at = 0; at < 2; at++) {
        float i0 = 1.f / lrow[at][0];
        float i1 = 1.f / lrow[at][1];
        int r0 = q0 + w * 32 + at * 16 + (lid >> 2);
        #pragma unroll
        for (int vn = 0; vn < 4; vn++) {
            int col = h * DHEAD + vn * 8 + (lid & 3) * 2;
            size_t g0 = ((size_t)(b * NTOK) + r0) * DD + col;
            size_t g1 = g0 + (size_t)8 * DD;
            uint32_t uh, ul;
            pack_split(O[at][vn][0] * i0, O[at][vn][1] * i0, uh, ul);
            *(uint32_t*)&aoh[g0] = uh; *(uint32_t*)&aol[g0] = ul;
            pack_split(O[at][vn][2] * i1, O[at][vn][3] * i1, uh, ul);
            *(uint32_t*)&aoh[g1] = uh; *(uint32_t*)&aol[g1] = ul;
        }
    }
}

// ---------------- kmeans ----------------
__global__ void initcent_kernel(const float* __restrict__ x, float* __restrict__ cent) {
    cent[(size_t)blockIdx.x * DD + threadIdx.x] = x[(size_t)blockIdx.x * DD + threadIdx.x];
}

__global__ __launch_bounds__(128)
void assign_kernel(const float* __restrict__ x, const float* __restrict__ cent,
                   const float* __restrict__ xsq, const float* __restrict__ csq,
                   int* __restrict__ lab) {
    __shared__ float Xs[32][33];
    __shared__ float Cs[64][32];
    __shared__ float bd[32][4];
    __shared__ int   bc[32][4];
    const int t = threadIdx.x;
    const int p = t & 31, cg = t >> 5;
    const int p0 = blockIdx.x * 32;

    float dot[16];
    #pragma unroll
    for (int c = 0; c < 16; c++) dot[c] = 0.f;

    for (int dc = 0; dc < DD; dc += 32) {
        #pragma unroll
        for (int i = 0; i < 2; i++) {
            int idx = i * 128 + t;
            int r = idx >> 3, c4 = (idx & 7) * 4;
            float4 v = *(const float4*)&x[(size_t)(p0 + r) * DD + dc + c4];
            Xs[r][c4 + 0] = v.x; Xs[r][c4 + 1] = v.y;
            Xs[r][c4 + 2] = v.z; Xs[r][c4 + 3] = v.w;
        }
        #pragma unroll
        for (int i = 0; i < 4; i++) {
            int idx = i * 128 + t;
            int r = idx >> 3, c4 = (idx & 7) * 4;
            *(float4*)&Cs[r][c4] = *(const float4*)&cent[(size_t)r * DD + dc + c4];
        }
        __syncthreads();
        #pragma unroll 4
        for (int d = 0; d < 32; d++) {
            float xv = Xs[p][d];
            #pragma unroll
            for (int c = 0; c < 16; c++) dot[c] += xv * Cs[cg * 16 + c][d];
        }
        __syncthreads();
    }

    float xs = xsq[p0 + p];
    float best = 3.4e38f;
    int bl = 0;
    #pragma unroll
    for (int c = 0; c < 16; c++) {
        float dd = xs - 2.f * dot[c] + csq[cg * 16 + c];
        if (dd < best) { best = dd; bl = cg * 16 + c; }
    }
    bd[p][cg] = best; bc[p][cg] = bl;
    __syncthreads();
    if (t < 32) {
        float b2 = bd[t][0]; int l2 = bc[t][0];
        #pragma unroll
        for (int g = 1; g < 4; g++)
            if (bd[t][g] < b2) { b2 = bd[t][g]; l2 = bc[t][g]; }
        lab[p0 + t] = l2;
    }
}

__global__ __launch_bounds__(256)
void segsum1_kernel(const float* __restrict__ x, const int* __restrict__ lab,
                    float* __restrict__ part, float* __restrict__ pcnt) {
    const int pb = blockIdx.x;
    const int c0 = blockIdx.y * 16;
    const int t = threadIdx.x;
    __shared__ float ps[16][DD];
    __shared__ int labs[128];
    #pragma unroll
    for (int i = 0; i < 16; i++) ps[i][t] = 0.f;
    if (t < 128) labs[t] = lab[pb * 128 + t];
    __syncthreads();
    const int p0 = pb * 128;
    for (int i = 0; i < 128; i++) {
        int l = labs[i] - c0;
        if ((unsigned)l < 16u)
            ps[l][t] += x[(size_t)(p0 + i) * DD + t];
    }
    for (int c = 0; c < 16; c++)
        part[((size_t)pb * KC + c0 + c) * DD + t] = ps[c][t];
    if (t < 16) {
        int cnt = 0;
        for (int i = 0; i < 128; i++) cnt += (labs[i] == c0 + t);
        pcnt[pb * KC + c0 + t] = (float)cnt;
    }
}

__global__ __launch_bounds__(256)
void update_csq_kernel(const float* __restrict__ part, const float* __restrict__ pcnt,
                       float* __restrict__ cent, float* __restrict__ csq) {
    const int c = blockIdx.x, t = threadIdx.x;
    __shared__ float scnt;
    float acc = 0.f;
    #pragma unroll 8
    for (int b2 = 0; b2 < SB; b2++) acc += part[((size_t)b2 * KC + c) * DD + t];
    if (t == 0) {
        float cc = 0.f;
        #pragma unroll 8
        for (int b2 = 0; b2 < SB; b2++) cc += pcnt[b2 * KC + c];
        scnt = cc;
    }
    __syncthreads();
    float cv = cent[(size_t)c * DD + t];
    float nv = (scnt > 0.f) ? acc / fmaxf(scnt, 1.f) : cv;
    cent[(size_t)c * DD + t] = nv;
    float s = blockSum256(nv * nv);
    if (t == 0) csq[c] = s;
}

__global__ void cproj_kernel(const float* __restrict__ cent, const float* __restrict__ kW,
                             const float* __restrict__ kb, float* __restrict__ cpro) {
    __shared__ float cr[DD];
    int c = blockIdx.x, t = threadIdx.x;
    cr[t] = cent[(size_t)c * DD + t];
    __syncthreads();
    float acc = kb[t];
    for (int d = 0; d < DD; d++) acc += cr[d] * kW[(size_t)d * DD + t];
    cpro[(size_t)c * DD + t] = acc;
}

__global__ void gather_kernel(const float* __restrict__ cproj, const int* __restrict__ lab,
                              float* __restrict__ out) {
    int p = blockIdx.x, t = threadIdx.x;
    out[(size_t)p * DD + t] = cproj[(size_t)lab[p] * DD + t];
}

// ---------------- host orchestration ----------------
extern "C" void kernel_launch(void* const* d_in, const int* in_sizes, int n_in,
                              void* d_out, int out_size) {
    const float* x_in = (const float*)d_in[0];
    const float* ln1g = (const float*)d_in[1];
    const float* ln1b = (const float*)d_in[2];
    const float* Wq   = (const float*)d_in[3];
    const float* Wkv  = (const float*)d_in[4];
    const float* Wo   = (const float*)d_in[5];
    const float* bo   = (const float*)d_in[6];
    const float* ln2g = (const float*)d_in[7];
    const float* ln2b = (const float*)d_in[8];
    const float* W1   = (const float*)d_in[9];
    const float* b1   = (const float*)d_in[10];
    const float* W2   = (const float*)d_in[11];
    const float* b2   = (const float*)d_in[12];
    const float* kW   = (const float*)d_in[13];
    const float* kb   = (const float*)d_in[14];
    float* out = (float*)d_out;

    float *p_x, *p_xsq, *p_cent, *p_csq, *p_cpro, *p_part, *p_pcnt, *p_psum;
    __nv_bfloat16 *p_qkvh, *p_qkvl, *p_vth, *p_vtl;
    __nv_bfloat16 *p_xnh, *p_xnl, *p_aoh, *p_aol, *p_hh, *p_hl, *p_wth, *p_wtl;
    int *p_lab;
    cudaGetSymbolAddress((void**)&p_x,    g_x);
    cudaGetSymbolAddress((void**)&p_qkvh, g_qkvh);
    cudaGetSymbolAddress((void**)&p_qkvl, g_qkvl);
    cudaGetSymbolAddress((void**)&p_vth,  g_vth);
    cudaGetSymbolAddress((void**)&p_vtl,  g_vtl);
    cudaGetSymbolAddress((void**)&p_xnh,  g_xnh);
    cudaGetSymbolAddress((void**)&p_xnl,  g_xnl);
    cudaGetSymbolAddress((void**)&p_aoh,  g_aoh);
    cudaGetSymbolAddress((void**)&p_aol,  g_aol);
    cudaGetSymbolAddress((void**)&p_hh,   g_hh);
    cudaGetSymbolAddress((void**)&p_hl,   g_hl);
    cudaGetSymbolAddress((void**)&p_wth,  g_wth);
    cudaGetSymbolAddress((void**)&p_wtl,  g_wtl);
    cudaGetSymbolAddress((void**)&p_psum, g_psum);
    cudaGetSymbolAddress((void**)&p_xsq,  g_xsq);
    cudaGetSymbolAddress((void**)&p_cent, g_cent);
    cudaGetSymbolAddress((void**)&p_csq,  g_csq);
    cudaGetSymbolAddress((void**)&p_lab,  g_lab);
    cudaGetSymbolAddress((void**)&p_cpro, g_cpro);
    cudaGetSymbolAddress((void**)&p_part, g_part);
    cudaGetSymbolAddress((void**)&p_pcnt, g_pcnt);

    cudaFuncSetAttribute(gemm_mma, cudaFuncAttributeMaxDynamicSharedMemorySize, GM_SMEM);
    cudaFuncSetAttribute(attn_mma, cudaFuncAttributeMaxDynamicSharedMemorySize, A_SMEM);

    dim3 tb32(32, 8);
    wsplit_kernel<<<dim3(8,  8, LL), tb32>>>(Wq,  p_wth + WQKV_OFF,         p_wtl + WQKV_OFF,         256, 256,  DD*DD,   WT_LAYER);
    wsplit_kernel<<<dim3(16, 8, LL), tb32>>>(Wkv, p_wth + WQKV_OFF + 65536, p_wtl + WQKV_OFF + 65536, 256, 512,  DD*2*DD, WT_LAYER);
    ln_kernel<<<NT / 8, 256>>>(x_in, ln1g, ln1b, p_xnh, p_xnl);
    wsplit_kernel<<<dim3(32, 8, LL), tb32>>>(W1,  p_wth + W1_OFF,           p_wtl + W1_OFF,           256, 1024, DD*MFF,  WT_LAYER);
    gemm_mma<<<dim3(6, 64), 256, GM_SMEM>>>(p_xnh, p_xnl, p_wth + WQKV_OFF, p_wtl + WQKV_OFF,
        nullptr, nullptr, nullptr, p_qkvh, p_qkvl, NT, QKVS, DD, DD, 0);
    wsplit_kernel<<<dim3(8,  8, LL), tb32>>>(Wo,  p_wth + WO_OFF,           p_wtl + WO_OFF,           256, 256,  DD*DD,   WT_LAYER);
    wsplit_kernel<<<dim3(8, 32, LL), tb32>>>(W2,  p_wth + W2_OFF,           p_wtl + W2_OFF,           1024, 256, MFF*DD,  WT_LAYER);

    for (int l = 0; l < LL; l++) {
        size_t wb = (size_t)l * WT_LAYER;
        const __nv_bfloat16* wqkvh = p_wth + wb + WQKV_OFF, *wqkvl = p_wtl + wb + WQKV_OFF;
        const __nv_bfloat16* woh   = p_wth + wb + WO_OFF,   *wol   = p_wtl + wb + WO_OFF;
        const __nv_bfloat16* w1h   = p_wth + wb + W1_OFF,   *w1l   = p_wtl + wb + W1_OFF;
        const __nv_bfloat16* w2h   = p_wth + wb + W2_OFF,   *w2l   = p_wtl + wb + W2_OFF;
        const float* xsrc = (l == 0) ? x_in : p_x;

        if (l > 0) {
            ln_kernel<<<NT / 8, 256>>>(xsrc, ln1g + l * DD, ln1b + l * DD, p_xnh, p_xnl);
            gemm_mma<<<dim3(6, 64), 256, GM_SMEM>>>(p_xnh, p_xnl, wqkvh, wqkvl,
                nullptr, nullptr, nullptr, p_qkvh, p_qkvl, NT, QKVS, DD, DD, 0);
        }
        // V transpose (once per layer)
        vtrans_kernel<<<dim3(NTOK / 256, HH, BB), 256>>>(p_qkvh, p_qkvl, p_vth, p_vtl);
        // attention -> split ao
        attn_mma<<<dim3(NTOK / 128, HH, BB), 128, A_SMEM>>>(p_qkvh, p_qkvl, p_vth, p_vtl, p_aoh, p_aol);
        // out proj + bias + residual (into x) — fused epilogue
        gemm_mma<<<dim3(2, 64), 256, GM_SMEM>>>(p_aoh, p_aol, woh, wol,
            bo + l * DD, xsrc, p_x, nullptr, nullptr, NT, DD, DD, DD, 0);
        // ln2 -> split xn
        ln_kernel<<<NT / 8, 256>>>(p_x, ln2g + l * DD, ln2b + l * DD, p_xnh, p_xnl);
        // ffn up + gelu -> split h
        gemm_mma<<<dim3(8, 64), 256, GM_SMEM>>>(p_xnh, p_xnl, w1h, w1l,
            b1 + l * MFF, nullptr, nullptr, p_hh, p_hl, NT, MFF, DD, DD, 1);
        // ffn down: split-K=4 partials, then deterministic reduction + bias + res
        gemm_mma<<<dim3(2, 64, NSPLIT), 256, GM_SMEM>>>(p_hh, p_hl, w2h, w2l,
            nullptr, nullptr, p_psum, nullptr, nullptr, NT, DD, MFF / NSPLIT, MFF, 0);
        ksum_kernel<NSPLIT><<<NT * DD / 4 / 256, 256>>>(p_psum, b2 + l * DD, p_x, p_x);
    }

    // ---- kmeans (fp32, deterministic) ----
    initcent_kernel<<<KC, 256>>>(p_x, p_cent);
    rowsumsq_kernel<<<NT / 8, 256>>>(p_x, p_xsq);
    rowsumsq_kernel<<<KC / 8, 256>>>(p_cent, p_csq);

    for (int it = 0; it < KM_IT; it++) {
        assign_kernel<<<NT / 32, 128>>>(p_x, p_cent, p_xsq, p_csq, p_lab);
        segsum1_kernel<<<dim3(SB, 4), 256>>>(p_x, p_lab, p_part, p_pcnt);
        update_csq_kernel<<<KC, 256>>>(p_part, p_pcnt, p_cent, p_csq);
    }
    assign_kernel<<<NT / 32, 128>>>(p_x, p_cent, p_xsq, p_csq, p_lab);

    cproj_kernel<<<KC, 256>>>(p_cent, kW, kb, p_cpro);
    gather_kernel<<<NT, 256>>>(p_cpro, p_lab, out);
}